// round 12
// baseline (speedup 1.0000x reference)
#include <cuda_runtime.h>
#include <cuda_bf16.h>
#include <math.h>
#include <cstdint>

// ---------------- problem constants ----------------
#define NQ      512
#define DIM     256
#define KQ      65536
#define KNN     200
#define NCLS    1000
#define INVT    (1.0f/0.07f)

#define NF      (KQ*DIM)
#define NL      KQ

#define OUT_FEAT_OFF 1
#define OUT_LAB_OFF  (1 + NF)
#define OUT_PTR_OFF  (1 + NF + NL)

// candidate filtering (int8 coarse pass)
#define CMAX        4096
#define S_QUANT     368.0f
#define INV_S2      (1.0f / (S_QUANT * S_QUANT))
#define T_COARSE    0.151f    // coarse (int8) filter threshold
#define T_SAFE      0.161f    // fast path valid iff 200th exact value >= this

// ---------------- device scratch ----------------
__device__ float g_sim[(size_t)NQ * KQ];                 // fallback scratch only
__device__ unsigned g_cidx[(size_t)NQ * CMAX];           // coarse survivor indices
__device__ unsigned long long g_cand[(size_t)NQ * CMAX]; // exact (val,idx) records
__device__ int  g_cnt[NQ];
__device__ int  g_correct;

// quantized int8 operands, tile-sequential permuted layout:
// tile t: [kb 0..7][row 0..127][8 permuted u32 words]  (8192 u32 = 32KB per tile)
__device__ uint32_t g_Aq[4 * 8192];
__device__ uint32_t g_Bq[(size_t)512 * 8192];

__device__ __forceinline__ unsigned orderf(float f) {
    unsigned u = __float_as_uint(f);
    return (u & 0x80000000u) ? ~u : (u | 0x80000000u);
}
__device__ __forceinline__ float unorderf(unsigned k) {
    return __uint_as_float((k & 0x80000000u) ? (k ^ 0x80000000u) : ~k);
}

#define CP16(dst, src) \
    asm volatile("cp.async.cg.shared.global [%0], [%1], 16;" :: "r"(dst), "l"(src) : "memory")
#define CPCOMMIT() asm volatile("cp.async.commit_group;" ::: "memory")

__device__ __forceinline__ uint32_t smem_u32(const void* p) {
    uint32_t a;
    asm("{ .reg .u64 t; cvta.to.shared.u64 t, %1; cvt.u32.u64 %0, t; }" : "=r"(a) : "l"(p));
    return a;
}

// ---------------- kernel 1: quantize fp32 -> int8 (+ zero counters) ----------
#define BGROUPS2 (KQ * 8)
#define AGROUPS2 (NQ * 8)

__device__ __forceinline__ uint32_t quant4(const float* e) {
    uint32_t w = 0;
    #pragma unroll
    for (int j = 0; j < 4; j++) {
        int q = __float2int_rn(e[j] * S_QUANT);
        q = max(-127, min(127, q));
        w |= ((uint32_t)(uint8_t)(int8_t)q) << (8 * j);
    }
    return w;
}

__global__ void __launch_bounds__(256)
convert_kernel(const float* __restrict__ A, const float* __restrict__ B) {
    int t = blockIdx.x * 256 + threadIdx.x;
    if (t < NQ) g_cnt[t] = 0;
    if (t == 0) g_correct = 0;

    const float* src;
    uint32_t* dst;
    if (t < BGROUPS2) {
        int row = t >> 3, kb = t & 7;
        src = B + (size_t)row * DIM + kb * 32;
        dst = g_Bq + (((size_t)(row >> 7) * 8 + kb) * 128 + (row & 127)) * 8;
    } else if (t < BGROUPS2 + AGROUPS2) {
        int u = t - BGROUPS2;
        int row = u >> 3, kb = u & 7;
        src = A + (size_t)row * DIM + kb * 32;
        dst = g_Aq + (((size_t)(row >> 7) * 8 + kb) * 128 + (row & 127)) * 8;
    } else return;

    float e[32];
    #pragma unroll
    for (int i = 0; i < 8; i++) {
        float4 v = *(const float4*)(src + i * 4);
        e[i*4+0] = v.x; e[i*4+1] = v.y; e[i*4+2] = v.z; e[i*4+3] = v.w;
    }
    uint32_t w[8];
    #pragma unroll
    for (int j = 0; j < 8; j++) {
        int p = ((j & 3) << 1) | (j >> 2);   // permute so (wj, wj+4) are adjacent
        w[p] = quant4(e + 4 * j);
    }
    *(uint4*)(dst)     = make_uint4(w[0], w[1], w[2], w[3]);
    *(uint4*)(dst + 4) = make_uint4(w[4], w[5], w[6], w[7]);
}

// ---------------- kernel 2: int8 IMMA coarse GEMM -> survivor indices -----------
#define TM 128
#define TN 128
#define GEMM_SMEM 65536                       // A 32KB | B 32KB (single stage, full K)

__device__ __forceinline__ void mma_s8(int* c, const uint32_t* a, const uint32_t* b) {
    asm volatile(
        "mma.sync.aligned.m16n8k32.row.col.s32.s8.s8.s32 "
        "{%0,%1,%2,%3}, {%4,%5,%6,%7}, {%8,%9}, {%0,%1,%2,%3};"
        : "+r"(c[0]), "+r"(c[1]), "+r"(c[2]), "+r"(c[3])
        : "r"(a[0]), "r"(a[1]), "r"(a[2]), "r"(a[3]), "r"(b[0]), "r"(b[1]));
}

__device__ __forceinline__ void cappend_idx(int qrow, float v, int col) {
    if (v > T_COARSE) {
        int slot = atomicAdd(&g_cnt[qrow], 1);
        if (slot < CMAX) g_cidx[(size_t)qrow * CMAX + slot] = (unsigned)col;
    }
}

__global__ void __launch_bounds__(256, 2)
gemm_tc_kernel() {
    extern __shared__ uint32_t smw[];
    const uint32_t sb = smem_u32(smw);
    const int tid  = threadIdx.x;
    const int lane = tid & 31;
    const int wid  = tid >> 5;
    const int gID  = lane >> 2;
    const int tig  = lane & 3;
    const int wm   = wid >> 2;
    const int wn   = wid & 3;
    const int m_t  = blockIdx.x;     // 0..3 (fast -> B tile L2 reuse)
    const int n_t  = blockIdx.y;     // 0..511

    int acc[4][4][4];
    #pragma unroll
    for (int m = 0; m < 4; m++)
        #pragma unroll
        for (int n = 0; n < 4; n++)
            #pragma unroll
            for (int r = 0; r < 4; r++) acc[m][n][r] = 0;

    // stage entire K: A tile 32KB @0, B tile 32KB @8192 words
    {
        const char* srcA = (const char*)(g_Aq + (size_t)m_t * 8192);
        const char* srcB = (const char*)(g_Bq + (size_t)n_t * 8192);
        #pragma unroll
        for (int j = 0; j < 8; j++)
            CP16(sb + tid * 16 + j * 4096, srcA + tid * 16 + j * 4096);
        #pragma unroll
        for (int j = 0; j < 8; j++)
            CP16(sb + 32768 + tid * 16 + j * 4096, srcB + tid * 16 + j * 4096);
        CPCOMMIT();
        asm volatile("cp.async.wait_group 0;" ::: "memory");
        __syncthreads();
    }

    const uint32_t* Aq = smw;
    const uint32_t* Bq = smw + 8192;

    #pragma unroll
    for (int kb = 0; kb < 8; kb++) {
        uint32_t afr[4][4];
        #pragma unroll
        for (int m = 0; m < 4; m++) {
            int row = wm * 64 + m * 16 + gID;
            uint2 v0 = *(const uint2*)(Aq + (kb * 128 + row) * 8 + tig * 2);
            uint2 v1 = *(const uint2*)(Aq + (kb * 128 + row + 8) * 8 + tig * 2);
            afr[m][0] = v0.x; afr[m][2] = v0.y;
            afr[m][1] = v1.x; afr[m][3] = v1.y;
        }
        uint32_t bfr[4][2];
        #pragma unroll
        for (int n = 0; n < 4; n++) {
            int rowb = wn * 32 + n * 8 + gID;
            uint2 v = *(const uint2*)(Bq + (kb * 128 + rowb) * 8 + tig * 2);
            bfr[n][0] = v.x; bfr[n][1] = v.y;
        }
        #pragma unroll
        for (int m = 0; m < 4; m++)
            #pragma unroll
            for (int n = 0; n < 4; n++)
                mma_s8(acc[m][n], afr[m], bfr[n]);
    }

    #pragma unroll
    for (int m = 0; m < 4; m++) {
        int row = m_t * TM + wm * 64 + m * 16 + gID;
        #pragma unroll
        for (int n = 0; n < 4; n++) {
            int col = n_t * TN + wn * 32 + n * 8 + tig * 2;
            cappend_idx(row,     (float)acc[m][n][0] * INV_S2, col);
            cappend_idx(row,     (float)acc[m][n][1] * INV_S2, col + 1);
            cappend_idx(row + 8, (float)acc[m][n][2] * INV_S2, col);
            cappend_idx(row + 8, (float)acc[m][n][3] * INV_S2, col + 1);
        }
    }
}

// ---------------- kernel 3: exact fp32 rescue of survivors ----------------
__global__ void __launch_bounds__(256)
rescue_kernel(const float* __restrict__ feats, const float* __restrict__ qf) {
    __shared__ float fvec[DIM];
    const int tid  = threadIdx.x;
    const int lane = tid & 31;
    const int wid  = tid >> 5;
    const int q    = blockIdx.x;
    const int cnt  = min(g_cnt[q], CMAX);

    for (int i = tid; i < DIM; i += 256) fvec[i] = feats[(size_t)q * DIM + i];
    __syncthreads();

    float a0 = fvec[lane * 8 + 0], a1 = fvec[lane * 8 + 1],
          a2 = fvec[lane * 8 + 2], a3 = fvec[lane * 8 + 3],
          a4 = fvec[lane * 8 + 4], a5 = fvec[lane * 8 + 5],
          a6 = fvec[lane * 8 + 6], a7 = fvec[lane * 8 + 7];

    for (int c = wid; c < cnt; c += 8) {
        unsigned idx = g_cidx[(size_t)q * CMAX + c];
        const float4* b4 = (const float4*)(qf + (size_t)idx * DIM) + lane * 2;
        float4 b0 = b4[0], b1 = b4[1];
        float d = a0 * b0.x;
        d = fmaf(a1, b0.y, d); d = fmaf(a2, b0.z, d); d = fmaf(a3, b0.w, d);
        d = fmaf(a4, b1.x, d); d = fmaf(a5, b1.y, d); d = fmaf(a6, b1.z, d);
        d = fmaf(a7, b1.w, d);
        #pragma unroll
        for (int o = 16; o > 0; o >>= 1)
            d += __shfl_xor_sync(0xFFFFFFFFu, d, o);
        if (lane == 0)
            g_cand[(size_t)q * CMAX + c] =
                ((unsigned long long)__float_as_uint(d) << 32) |
                (unsigned)(idx ^ 0xFFFFu);
    }
}

// ---------------- kernel 4: top-200 + vote + argmax (guarded fast path) ----------------
#define TK_BINS 2048
#define BND_MAX 1024
#define TOPK_SMEM (32768 + 8192 + 4096)

__device__ __forceinline__ int val_bin(unsigned bits) {
    if (bits <= 0x3E000000u) return 0;
    unsigned b = (bits - 0x3E000000u) >> 14;
    return (b > TK_BINS - 1) ? (TK_BINS - 1) : (int)b;
}

__global__ void __launch_bounds__(256)
topk_kernel(const int* __restrict__ qlabels, const int* __restrict__ labels,
            const float* __restrict__ feats, const float* __restrict__ qf) {
    extern __shared__ char smem[];
    unsigned long long* cand = (unsigned long long*)smem;
    unsigned* hist = (unsigned*)(smem + 32768);
    float* scores  = (float*)(smem + 32768 + 8192);

    __shared__ unsigned long long bnd[BND_MAX];
    __shared__ unsigned s_gsum[256];
    __shared__ int s_B, s_cGreater, s_bcnt;
    __shared__ float s_bv[256];
    __shared__ int   s_bi[256];

    const int tid = threadIdx.x;
    const int q   = blockIdx.x;
    const int cnt = g_cnt[q];
    bool fast = (cnt >= KNN && cnt <= CMAX);
    bool row_built = false;

    for (int i = tid; i < 1024; i += 256) scores[i] = 0.f;
    if (fast) {
        for (int i = tid; i < cnt; i += 256)
            cand[i] = g_cand[(size_t)q * CMAX + i];
    }

    int B, need;
    while (true) {
        for (int i = tid; i < TK_BINS; i += 256) hist[i] = 0u;
        if (tid == 0) s_bcnt = 0;
        __syncthreads();

        if (fast) {
            for (int i = tid; i < cnt; i += 256)
                atomicAdd(&hist[val_bin((unsigned)(cand[i] >> 32))], 1u);
        } else {
            if (!row_built) {
                float* fvec = (float*)bnd;
                for (int i = tid; i < DIM; i += 256) fvec[i] = feats[(size_t)q * DIM + i];
                __syncthreads();
                float* row = g_sim + (size_t)q * KQ;
                for (int i = tid; i < KQ; i += 256) {
                    const float4* b4 = (const float4*)(qf + (size_t)i * DIM);
                    float d = 0.f;
                    #pragma unroll 8
                    for (int k = 0; k < DIM / 4; k++) {
                        float4 bv = b4[k];
                        d = fmaf(fvec[4*k+0], bv.x, d);
                        d = fmaf(fvec[4*k+1], bv.y, d);
                        d = fmaf(fvec[4*k+2], bv.z, d);
                        d = fmaf(fvec[4*k+3], bv.w, d);
                    }
                    row[i] = d;
                }
                row_built = true;
                __syncthreads();
            }
            const float* row = g_sim + (size_t)q * KQ;
            for (int i = tid; i < KQ; i += 256)
                atomicAdd(&hist[orderf(row[i]) >> 21], 1u);
        }
        __syncthreads();

        unsigned gs = 0;
        #pragma unroll 8
        for (int b = 0; b < 8; b++) gs += hist[tid * 8 + b];
        s_gsum[tid] = gs;
        __syncthreads();

        if (tid == 0) {
            unsigned cum = 0; int Bl = 0; unsigned cG = 0;
            for (int g = 255; g >= 0; --g) {
                if (cum + s_gsum[g] >= KNN) {
                    for (int b = g * 8 + 7; b >= g * 8; --b) {
                        if (cum + hist[b] >= KNN) { Bl = b; cG = cum; break; }
                        cum += hist[b];
                    }
                    break;
                }
                cum += s_gsum[g];
            }
            s_B = Bl; s_cGreater = (int)cG;
        }
        __syncthreads();
        B = s_B; need = KNN - s_cGreater;

        if (fast) {
            // safety: 200th exact value must clear filter + quantization bound
            float blow = __uint_as_float(0x3E000000u + ((unsigned)B << 14));
            if (blow < T_SAFE) { fast = false; __syncthreads(); continue; }
        }
        break;
    }

    if (fast) {
        for (int i = tid; i < cnt; i += 256) {
            unsigned long long c = cand[i];
            unsigned bits = (unsigned)(c >> 32);
            int bin = val_bin(bits);
            if (bin > B) {
                int idx = ((int)((unsigned)c & 0xFFFFu)) ^ 0xFFFF;
                atomicAdd(&scores[qlabels[idx]], expf(__uint_as_float(bits) * INVT));
            } else if (bin == B) {
                int p = atomicAdd(&s_bcnt, 1);
                if (p < BND_MAX) bnd[p] = c;
            }
        }
    } else {
        const float* row = g_sim + (size_t)q * KQ;
        for (int i = tid; i < KQ; i += 256) {
            float v = row[i];
            unsigned k = orderf(v);
            int bin = (int)(k >> 21);
            if (bin > B) {
                atomicAdd(&scores[qlabels[i]], expf(v * INVT));
            } else if (bin == B) {
                int p = atomicAdd(&s_bcnt, 1);
                if (p < BND_MAX)
                    bnd[p] = ((unsigned long long)k << 32) | (unsigned)(i ^ 0xFFFF);
            }
        }
    }
    __syncthreads();

    int bcnt = min(s_bcnt, BND_MAX);
    if (need > bcnt) need = bcnt;
    for (int i = tid; i < bcnt; i += 256) {
        unsigned long long mine = bnd[i];
        int rank = 0;
        for (int j = 0; j < bcnt; j++) rank += (bnd[j] > mine);
        if (rank < need) {
            unsigned hi = (unsigned)(mine >> 32);
            float v = fast ? __uint_as_float(hi) : unorderf(hi);
            int idx = ((int)((unsigned)mine & 0xFFFFu)) ^ 0xFFFF;
            atomicAdd(&scores[qlabels[idx]], expf(v * INVT));
        }
    }
    __syncthreads();

    float best = -1.f; int bi = NCLS;
    for (int c = tid; c < NCLS; c += 256) {
        float v = scores[c];
        if (v > best) { best = v; bi = c; }
    }
    s_bv[tid] = best; s_bi[tid] = bi;
    __syncthreads();
    for (int s = 128; s > 0; s >>= 1) {
        if (tid < s) {
            float ov = s_bv[tid + s]; int oi = s_bi[tid + s];
            if (ov > s_bv[tid] || (ov == s_bv[tid] && oi < s_bi[tid])) {
                s_bv[tid] = ov; s_bi[tid] = oi;
            }
        }
        __syncthreads();
    }
    if (tid == 0 && s_bi[0] == labels[q]) atomicAdd(&g_correct, 1);
}

// ---------------- kernel 5: queue update copy (+ scalars; runs after topk) ----------------
__global__ void __launch_bounds__(256)
copy_kernel(const float* __restrict__ feats, const int* __restrict__ labels,
            const float* __restrict__ qf, const int* __restrict__ ql,
            const int* __restrict__ qptr, float* __restrict__ out) {
    const int ptr = qptr[0];
    if (blockIdx.x == 0 && threadIdx.x == 0) {
        out[0] = (float)g_correct * (1.0f / (float)NQ);
        out[OUT_PTR_OFF] = (float)((ptr + NQ) % KQ);
    }
    size_t i4 = (size_t)blockIdx.x * 256 + threadIdx.x;
    if (i4 < (size_t)(NF / 4)) {
        int r = (int)(i4 >> 6);
        int rel = r - ptr; if (rel < 0) rel += KQ;
        float4 v = (rel < NQ) ? ((const float4*)feats)[(size_t)rel * 64 + (i4 & 63)]
                              : ((const float4*)qf)[i4];
        float* o = out + OUT_FEAT_OFF + i4 * 4;
        o[0] = v.x; o[1] = v.y; o[2] = v.z; o[3] = v.w;
    } else if (i4 < (size_t)(NF / 4 + NL / 4)) {
        int j4 = (int)(i4 - NF / 4);
        int4 lv = ((const int4*)ql)[j4];
        int base = j4 * 4;
        float* o = out + OUT_LAB_OFF + base;
        #pragma unroll
        for (int k = 0; k < 4; k++) {
            int i = base + k;
            int rel = i - ptr; if (rel < 0) rel += KQ;
            int lab = (rel < NQ) ? labels[rel] : ((const int*)&lv)[k];
            o[k] = (float)lab;
        }
    }
}

// ---------------- launch ----------------
extern "C" void kernel_launch(void* const* d_in, const int* in_sizes, int n_in,
                              void* d_out, int out_size) {
    const float* feats  = (const float*)d_in[0];
    const int*   labels = (const int*)d_in[1];
    const float* qf     = (const float*)d_in[2];
    const int*   ql     = (const int*)d_in[3];
    const int*   qptr   = (const int*)d_in[4];
    float* out = (float*)d_out;

    cudaFuncSetAttribute(gemm_tc_kernel, cudaFuncAttributeMaxDynamicSharedMemorySize, GEMM_SMEM);
    cudaFuncSetAttribute(topk_kernel, cudaFuncAttributeMaxDynamicSharedMemorySize, TOPK_SMEM);

    convert_kernel<<<(BGROUPS2 + AGROUPS2 + 255) / 256, 256>>>(feats, qf);
    gemm_tc_kernel<<<dim3(NQ / TM, KQ / TN), 256, GEMM_SMEM>>>();
    rescue_kernel<<<NQ, 256>>>(feats, qf);
    topk_kernel<<<NQ, 256, TOPK_SMEM>>>(ql, labels, feats, qf);

    int total4 = NF / 4 + NL / 4;
    copy_kernel<<<(total4 + 255) / 256, 256>>>(feats, labels, qf, ql, qptr, out);
    (void)in_sizes; (void)n_in; (void)out_size;
}

// round 13
// speedup vs baseline: 1.4396x; 1.4396x over previous
#include <cuda_runtime.h>
#include <cuda_bf16.h>
#include <math.h>
#include <cstdint>

// ---------------- problem constants ----------------
#define NQ      512
#define DIM     256
#define KQ      65536
#define KNN     200
#define NCLS    1000
#define INVT    (1.0f/0.07f)

#define NF      (KQ*DIM)
#define NL      KQ

#define OUT_FEAT_OFF 1
#define OUT_LAB_OFF  (1 + NF)
#define OUT_PTR_OFF  (1 + NF + NL)

// candidate filtering
#define CMAX        4096
#define T_COARSE    0.160f    // coarse (hi*hi) filter threshold
#define T_SAFE      0.1633f   // fast path valid iff 200th exact value >= this

// ---------------- device scratch ----------------
__device__ float g_sim[(size_t)NQ * KQ];                 // fallback scratch only
__device__ unsigned g_cidx[(size_t)NQ * CMAX];           // coarse survivor indices
__device__ unsigned long long g_cand[(size_t)NQ * CMAX]; // exact (val,idx) records
__device__ int  g_cnt[NQ];
__device__ int  g_correct;

// pre-converted bf16 hi operands, tile-sequential permuted layout
__device__ uint32_t g_Ah[65536];
__device__ uint32_t g_Bh[(size_t)8388608];

__device__ __forceinline__ unsigned orderf(float f) {
    unsigned u = __float_as_uint(f);
    return (u & 0x80000000u) ? ~u : (u | 0x80000000u);
}
__device__ __forceinline__ float unorderf(unsigned k) {
    return __uint_as_float((k & 0x80000000u) ? (k ^ 0x80000000u) : ~k);
}

#define CP16(dst, src) \
    asm volatile("cp.async.cg.shared.global [%0], [%1], 16;" :: "r"(dst), "l"(src) : "memory")
#define CPCOMMIT() asm volatile("cp.async.commit_group;" ::: "memory")

__device__ __forceinline__ uint32_t smem_u32(const void* p) {
    uint32_t a;
    asm("{ .reg .u64 t; cvta.to.shared.u64 t, %1; cvt.u32.u64 %0, t; }" : "=r"(a) : "l"(p));
    return a;
}

// ---------------- kernel 1: pre-convert fp32 -> bf16 hi (+ zero counters) ----------
#define BGROUPS (KQ * 16)
#define AGROUPS (NQ * 16)

__global__ void __launch_bounds__(256)
convert_kernel(const float* __restrict__ A, const float* __restrict__ B) {
    int t = blockIdx.x * 256 + threadIdx.x;
    if (t < NQ) g_cnt[t] = 0;
    if (t == 0) g_correct = 0;

    const float* src;
    uint32_t* dh;
    if (t < BGROUPS) {
        int row = t >> 4, k16 = t & 15;
        src = B + (size_t)row * DIM + k16 * 16;
        size_t g = ((size_t)(row >> 7) * 16 + k16) * 128 + (row & 127);
        dh = g_Bh + g * 8;
    } else if (t < BGROUPS + AGROUPS) {
        int u = t - BGROUPS;
        int row = u >> 4, k16 = u & 15;
        src = A + (size_t)row * DIM + k16 * 16;
        size_t g = ((size_t)(row >> 7) * 16 + k16) * 128 + (row & 127);
        dh = g_Ah + g * 8;
    } else return;

    float e[16];
    #pragma unroll
    for (int i = 0; i < 4; i++) {
        float4 v = *(const float4*)(src + i * 4);
        e[i*4+0] = v.x; e[i*4+1] = v.y; e[i*4+2] = v.z; e[i*4+3] = v.w;
    }
    uint32_t h[8];
    #pragma unroll
    for (int q = 0; q < 8; q++) {
        int p = ((q & 3) << 1) | (q >> 2);
        __nv_bfloat162 hh = __floats2bfloat162_rn(e[2*q], e[2*q+1]);
        h[p] = *(uint32_t*)&hh;
    }
    *(uint4*)(dh)     = make_uint4(h[0], h[1], h[2], h[3]);
    *(uint4*)(dh + 4) = make_uint4(h[4], h[5], h[6], h[7]);
}

// ---------------- kernel 2: 1-pass coarse HMMA GEMM -> survivor indices -----------
#define TM 128
#define TN 128
#define NCHUNK 8
#define STAGE_W 4096
#define GEMM_SMEM (2 * STAGE_W * 4)

__device__ __forceinline__ void mma16816(float* c, const uint32_t* a, const uint32_t* b) {
    asm volatile(
        "mma.sync.aligned.m16n8k16.row.col.f32.bf16.bf16.f32 "
        "{%0,%1,%2,%3}, {%4,%5,%6,%7}, {%8,%9}, {%0,%1,%2,%3};"
        : "+f"(c[0]), "+f"(c[1]), "+f"(c[2]), "+f"(c[3])
        : "r"(a[0]), "r"(a[1]), "r"(a[2]), "r"(a[3]), "r"(b[0]), "r"(b[1]));
}

__device__ __forceinline__ void cappend_idx(int qrow, float v, int col) {
    if (v > T_COARSE) {
        int slot = atomicAdd(&g_cnt[qrow], 1);
        if (slot < CMAX) g_cidx[(size_t)qrow * CMAX + slot] = (unsigned)col;
    }
}

__global__ void __launch_bounds__(256, 2)
gemm_tc_kernel() {
    extern __shared__ uint32_t smw[];
    const uint32_t sb = smem_u32(smw);
    const int tid  = threadIdx.x;
    const int lane = tid & 31;
    const int wid  = tid >> 5;
    const int gID  = lane >> 2;
    const int tig  = lane & 3;
    const int wm   = wid >> 2;
    const int wn   = wid & 3;
    const int m_t  = blockIdx.x;     // 0..3 (fast -> B tile L2 reuse)
    const int n_t  = blockIdx.y;     // 0..511

    float acc[4][4][4];
    #pragma unroll
    for (int m = 0; m < 4; m++)
        #pragma unroll
        for (int n = 0; n < 4; n++)
            #pragma unroll
            for (int r = 0; r < 4; r++) acc[m][n][r] = 0.f;

    const uint32_t* srcA = g_Ah + ((size_t)m_t * 16) * 1024;
    const uint32_t* srcB = g_Bh + ((size_t)n_t * 16) * 1024;

    auto stage = [&](int ch, int buf) {
        uint32_t d0 = sb + buf * (STAGE_W * 4);
        size_t goff = (size_t)(2 * ch) * 1024;
        const uint32_t* s[2] = { srcA + goff, srcB + goff };
        #pragma unroll
        for (int tl = 0; tl < 2; tl++) {
            uint32_t d = d0 + tl * 8192 + tid * 16;
            const char* sp = (const char*)s[tl] + tid * 16;
            CP16(d, sp);
            CP16(d + 4096, sp + 4096);
        }
    };

    stage(0, 0); CPCOMMIT();
    stage(1, 1); CPCOMMIT();

    for (int ch = 0; ch < NCHUNK; ++ch) {
        asm volatile("cp.async.wait_group 1;" ::: "memory");
        __syncthreads();

        const uint32_t* Ah = smw + (ch & 1) * STAGE_W;
        const uint32_t* Bh = Ah + 2048;

        #pragma unroll
        for (int s = 0; s < 2; s++) {
            uint32_t afr[4][4];
            #pragma unroll
            for (int m = 0; m < 4; m++) {
                int row = wm * 64 + m * 16 + gID;
                uint2 v0 = *(const uint2*)(Ah + (s * 128 + row) * 8 + tig * 2);
                uint2 v1 = *(const uint2*)(Ah + (s * 128 + row + 8) * 8 + tig * 2);
                afr[m][0] = v0.x; afr[m][2] = v0.y;
                afr[m][1] = v1.x; afr[m][3] = v1.y;
            }
            uint32_t bfr[4][2];
            #pragma unroll
            for (int n = 0; n < 4; n++) {
                int rowb = wn * 32 + n * 8 + gID;
                uint2 v = *(const uint2*)(Bh + (s * 128 + rowb) * 8 + tig * 2);
                bfr[n][0] = v.x; bfr[n][1] = v.y;
            }
            #pragma unroll
            for (int m = 0; m < 4; m++)
                #pragma unroll
                for (int n = 0; n < 4; n++)
                    mma16816(acc[m][n], afr[m], bfr[n]);
        }
        __syncthreads();

        if (ch + 2 < NCHUNK) stage(ch + 2, ch & 1);
        CPCOMMIT();
    }

    #pragma unroll
    for (int m = 0; m < 4; m++) {
        int row = m_t * TM + wm * 64 + m * 16 + gID;
        #pragma unroll
        for (int n = 0; n < 4; n++) {
            int col = n_t * TN + wn * 32 + n * 8 + tig * 2;
            cappend_idx(row,     acc[m][n][0], col);
            cappend_idx(row,     acc[m][n][1], col + 1);
            cappend_idx(row + 8, acc[m][n][2], col);
            cappend_idx(row + 8, acc[m][n][3], col + 1);
        }
    }
}

// ---------------- kernel 3: exact fp32 rescue of survivors ----------------
__global__ void __launch_bounds__(256)
rescue_kernel(const float* __restrict__ feats, const float* __restrict__ qf) {
    __shared__ float fvec[DIM];
    const int tid  = threadIdx.x;
    const int lane = tid & 31;
    const int wid  = tid >> 5;
    const int q    = blockIdx.x;
    const int cnt  = min(g_cnt[q], CMAX);

    for (int i = tid; i < DIM; i += 256) fvec[i] = feats[(size_t)q * DIM + i];
    __syncthreads();

    float a0 = fvec[lane * 8 + 0], a1 = fvec[lane * 8 + 1],
          a2 = fvec[lane * 8 + 2], a3 = fvec[lane * 8 + 3],
          a4 = fvec[lane * 8 + 4], a5 = fvec[lane * 8 + 5],
          a6 = fvec[lane * 8 + 6], a7 = fvec[lane * 8 + 7];

    for (int c = wid; c < cnt; c += 8) {
        unsigned idx = g_cidx[(size_t)q * CMAX + c];
        const float4* b4 = (const float4*)(qf + (size_t)idx * DIM) + lane * 2;
        float4 b0 = b4[0], b1 = b4[1];
        float d = a0 * b0.x;
        d = fmaf(a1, b0.y, d); d = fmaf(a2, b0.z, d); d = fmaf(a3, b0.w, d);
        d = fmaf(a4, b1.x, d); d = fmaf(a5, b1.y, d); d = fmaf(a6, b1.z, d);
        d = fmaf(a7, b1.w, d);
        #pragma unroll
        for (int o = 16; o > 0; o >>= 1)
            d += __shfl_xor_sync(0xFFFFFFFFu, d, o);
        if (lane == 0)
            g_cand[(size_t)q * CMAX + c] =
                ((unsigned long long)__float_as_uint(d) << 32) |
                (unsigned)(idx ^ 0xFFFFu);
    }
}

// ---------------- kernel 4: top-200 + vote + argmax (guarded fast path) ----------------
#define TK_BINS 2048
#define BND_MAX 1024
#define TOPK_SMEM (32768 + 8192 + 4096)

__device__ __forceinline__ int val_bin(unsigned bits) {
    if (bits <= 0x3E000000u) return 0;
    unsigned b = (bits - 0x3E000000u) >> 14;
    return (b > TK_BINS - 1) ? (TK_BINS - 1) : (int)b;
}

__global__ void __launch_bounds__(256)
topk_kernel(const int* __restrict__ qlabels, const int* __restrict__ labels,
            const float* __restrict__ feats, const float* __restrict__ qf) {
    extern __shared__ char smem[];
    unsigned long long* cand = (unsigned long long*)smem;
    unsigned* hist = (unsigned*)(smem + 32768);
    float* scores  = (float*)(smem + 32768 + 8192);

    __shared__ unsigned long long bnd[BND_MAX];
    __shared__ unsigned s_gsum[256];
    __shared__ int s_B, s_cGreater, s_bcnt;
    __shared__ float s_bv[256];
    __shared__ int   s_bi[256];

    const int tid = threadIdx.x;
    const int q   = blockIdx.x;
    const int cnt = g_cnt[q];
    bool fast = (cnt >= KNN && cnt <= CMAX);
    bool row_built = false;

    for (int i = tid; i < 1024; i += 256) scores[i] = 0.f;
    if (fast) {
        for (int i = tid; i < cnt; i += 256)
            cand[i] = g_cand[(size_t)q * CMAX + i];
    }

    int B, need;
    while (true) {
        for (int i = tid; i < TK_BINS; i += 256) hist[i] = 0u;
        if (tid == 0) s_bcnt = 0;
        __syncthreads();

        if (fast) {
            for (int i = tid; i < cnt; i += 256)
                atomicAdd(&hist[val_bin((unsigned)(cand[i] >> 32))], 1u);
        } else {
            if (!row_built) {
                float* fvec = (float*)bnd;
                for (int i = tid; i < DIM; i += 256) fvec[i] = feats[(size_t)q * DIM + i];
                __syncthreads();
                float* row = g_sim + (size_t)q * KQ;
                for (int i = tid; i < KQ; i += 256) {
                    const float4* b4 = (const float4*)(qf + (size_t)i * DIM);
                    float d = 0.f;
                    #pragma unroll 8
                    for (int k = 0; k < DIM / 4; k++) {
                        float4 bv = b4[k];
                        d = fmaf(fvec[4*k+0], bv.x, d);
                        d = fmaf(fvec[4*k+1], bv.y, d);
                        d = fmaf(fvec[4*k+2], bv.z, d);
                        d = fmaf(fvec[4*k+3], bv.w, d);
                    }
                    row[i] = d;
                }
                row_built = true;
                __syncthreads();
            }
            const float* row = g_sim + (size_t)q * KQ;
            for (int i = tid; i < KQ; i += 256)
                atomicAdd(&hist[orderf(row[i]) >> 21], 1u);
        }
        __syncthreads();

        unsigned gs = 0;
        #pragma unroll 8
        for (int b = 0; b < 8; b++) gs += hist[tid * 8 + b];
        s_gsum[tid] = gs;
        __syncthreads();

        if (tid == 0) {
            unsigned cum = 0; int Bl = 0; unsigned cG = 0;
            for (int g = 255; g >= 0; --g) {
                if (cum + s_gsum[g] >= KNN) {
                    for (int b = g * 8 + 7; b >= g * 8; --b) {
                        if (cum + hist[b] >= KNN) { Bl = b; cG = cum; break; }
                        cum += hist[b];
                    }
                    break;
                }
                cum += s_gsum[g];
            }
            s_B = Bl; s_cGreater = (int)cG;
        }
        __syncthreads();
        B = s_B; need = KNN - s_cGreater;

        if (fast) {
            float blow = __uint_as_float(0x3E000000u + ((unsigned)B << 14));
            if (blow < T_SAFE) { fast = false; __syncthreads(); continue; }
        }
        break;
    }

    if (fast) {
        for (int i = tid; i < cnt; i += 256) {
            unsigned long long c = cand[i];
            unsigned bits = (unsigned)(c >> 32);
            int bin = val_bin(bits);
            if (bin > B) {
                int idx = ((int)((unsigned)c & 0xFFFFu)) ^ 0xFFFF;
                atomicAdd(&scores[qlabels[idx]], expf(__uint_as_float(bits) * INVT));
            } else if (bin == B) {
                int p = atomicAdd(&s_bcnt, 1);
                if (p < BND_MAX) bnd[p] = c;
            }
        }
    } else {
        const float* row = g_sim + (size_t)q * KQ;
        for (int i = tid; i < KQ; i += 256) {
            float v = row[i];
            unsigned k = orderf(v);
            int bin = (int)(k >> 21);
            if (bin > B) {
                atomicAdd(&scores[qlabels[i]], expf(v * INVT));
            } else if (bin == B) {
                int p = atomicAdd(&s_bcnt, 1);
                if (p < BND_MAX)
                    bnd[p] = ((unsigned long long)k << 32) | (unsigned)(i ^ 0xFFFF);
            }
        }
    }
    __syncthreads();

    int bcnt = min(s_bcnt, BND_MAX);
    if (need > bcnt) need = bcnt;
    for (int i = tid; i < bcnt; i += 256) {
        unsigned long long mine = bnd[i];
        int rank = 0;
        for (int j = 0; j < bcnt; j++) rank += (bnd[j] > mine);
        if (rank < need) {
            unsigned hi = (unsigned)(mine >> 32);
            float v = fast ? __uint_as_float(hi) : unorderf(hi);
            int idx = ((int)((unsigned)mine & 0xFFFFu)) ^ 0xFFFF;
            atomicAdd(&scores[qlabels[idx]], expf(v * INVT));
        }
    }
    __syncthreads();

    float best = -1.f; int bi = NCLS;
    for (int c = tid; c < NCLS; c += 256) {
        float v = scores[c];
        if (v > best) { best = v; bi = c; }
    }
    s_bv[tid] = best; s_bi[tid] = bi;
    __syncthreads();
    for (int s = 128; s > 0; s >>= 1) {
        if (tid < s) {
            float ov = s_bv[tid + s]; int oi = s_bi[tid + s];
            if (ov > s_bv[tid] || (ov == s_bv[tid] && oi < s_bi[tid])) {
                s_bv[tid] = ov; s_bi[tid] = oi;
            }
        }
        __syncthreads();
    }
    if (tid == 0 && s_bi[0] == labels[q]) atomicAdd(&g_correct, 1);
}

// ---------------- kernel 5: queue update copy (no scalars; may run concurrently) -------
__global__ void __launch_bounds__(256)
copy_kernel(const float* __restrict__ feats, const int* __restrict__ labels,
            const float* __restrict__ qf, const int* __restrict__ ql,
            const int* __restrict__ qptr, float* __restrict__ out) {
    const int ptr = qptr[0];
    size_t i4 = (size_t)blockIdx.x * 256 + threadIdx.x;
    if (i4 < (size_t)(NF / 4)) {
        int r = (int)(i4 >> 6);
        int rel = r - ptr; if (rel < 0) rel += KQ;
        float4 v = (rel < NQ) ? ((const float4*)feats)[(size_t)rel * 64 + (i4 & 63)]
                              : ((const float4*)qf)[i4];
        float* o = out + OUT_FEAT_OFF + i4 * 4;
        o[0] = v.x; o[1] = v.y; o[2] = v.z; o[3] = v.w;
    } else if (i4 < (size_t)(NF / 4 + NL / 4)) {
        int j4 = (int)(i4 - NF / 4);
        int4 lv = ((const int4*)ql)[j4];
        int base = j4 * 4;
        float* o = out + OUT_LAB_OFF + base;
        #pragma unroll
        for (int k = 0; k < 4; k++) {
            int i = base + k;
            int rel = i - ptr; if (rel < 0) rel += KQ;
            int lab = (rel < NQ) ? labels[rel] : ((const int*)&lv)[k];
            o[k] = (float)lab;
        }
    }
}

// ---------------- kernel 6: scalars (after topk) ----------------
__global__ void finalize_kernel(const int* __restrict__ qptr, float* __restrict__ out) {
    out[0] = (float)g_correct * (1.0f / (float)NQ);
    out[OUT_PTR_OFF] = (float)((qptr[0] + NQ) % KQ);
}

// ---------------- launch ----------------
extern "C" void kernel_launch(void* const* d_in, const int* in_sizes, int n_in,
                              void* d_out, int out_size) {
    const float* feats  = (const float*)d_in[0];
    const int*   labels = (const int*)d_in[1];
    const float* qf     = (const float*)d_in[2];
    const int*   ql     = (const int*)d_in[3];
    const int*   qptr   = (const int*)d_in[4];
    float* out = (float*)d_out;

    cudaFuncSetAttribute(gemm_tc_kernel, cudaFuncAttributeMaxDynamicSharedMemorySize, GEMM_SMEM);
    cudaFuncSetAttribute(topk_kernel, cudaFuncAttributeMaxDynamicSharedMemorySize, TOPK_SMEM);

    // lazy one-time side-stream setup (host objects only; no device memory)
    static cudaStream_t s2 = nullptr;
    static cudaEvent_t evF = nullptr, evJ = nullptr;
    static bool tried = false;
    if (!tried) {
        tried = true;
        if (cudaStreamCreateWithFlags(&s2, cudaStreamNonBlocking) != cudaSuccess) s2 = nullptr;
        if (s2) {
            if (cudaEventCreateWithFlags(&evF, cudaEventDisableTiming) != cudaSuccess ||
                cudaEventCreateWithFlags(&evJ, cudaEventDisableTiming) != cudaSuccess) {
                s2 = nullptr;
            }
        }
    }

    int total4 = NF / 4 + NL / 4;
    int copy_blocks = (total4 + 255) / 256;

    if (s2) {
        // fork: copy depends only on inputs -> run concurrently with the pipeline
        cudaEventRecord(evF, 0);
        cudaStreamWaitEvent(s2, evF, 0);
        copy_kernel<<<copy_blocks, 256, 0, s2>>>(feats, labels, qf, ql, qptr, out);
        cudaEventRecord(evJ, s2);
    }

    convert_kernel<<<(BGROUPS + AGROUPS + 255) / 256, 256>>>(feats, qf);
    gemm_tc_kernel<<<dim3(NQ / TM, KQ / TN), 256, GEMM_SMEM>>>();
    rescue_kernel<<<NQ, 256>>>(feats, qf);
    topk_kernel<<<NQ, 256, TOPK_SMEM>>>(ql, labels, feats, qf);

    if (s2) {
        cudaStreamWaitEvent(0, evJ, 0);     // join before final scalar write
    } else {
        copy_kernel<<<copy_blocks, 256>>>(feats, labels, qf, ql, qptr, out);
    }
    finalize_kernel<<<1, 1>>>(qptr, out);
    (void)in_sizes; (void)n_in; (void)out_size;
}

// round 14
// speedup vs baseline: 1.4510x; 1.0080x over previous
#include <cuda_runtime.h>
#include <cuda_bf16.h>
#include <math.h>
#include <cstdint>

// ---------------- problem constants ----------------
#define NQ      512
#define DIM     256
#define KQ      65536
#define KNN     200
#define NCLS    1000
#define INVT    (1.0f/0.07f)

#define NF      (KQ*DIM)
#define NL      KQ

#define OUT_FEAT_OFF 1
#define OUT_LAB_OFF  (1 + NF)
#define OUT_PTR_OFF  (1 + NF + NL)

// candidate filtering
#define CMAX        4096
#define T_COARSE    0.160f    // coarse (hi*hi) filter threshold
#define T_SAFE      0.1633f   // fast path valid iff 200th exact value >= this

// ---------------- device scratch ----------------
__device__ float g_sim[(size_t)NQ * KQ];                 // fallback scratch only
__device__ unsigned g_cidx[(size_t)NQ * CMAX];           // coarse survivor indices
__device__ unsigned long long g_cand[(size_t)NQ * CMAX]; // exact (val,idx) records
__device__ int  g_cnt[NQ];
__device__ int  g_correct;

// pre-converted bf16 hi operands, tile-sequential permuted layout
__device__ uint32_t g_Ah[65536];
__device__ uint32_t g_Bh[(size_t)8388608];

__device__ __forceinline__ unsigned orderf(float f) {
    unsigned u = __float_as_uint(f);
    return (u & 0x80000000u) ? ~u : (u | 0x80000000u);
}
__device__ __forceinline__ float unorderf(unsigned k) {
    return __uint_as_float((k & 0x80000000u) ? (k ^ 0x80000000u) : ~k);
}

#define CP16(dst, src) \
    asm volatile("cp.async.cg.shared.global [%0], [%1], 16;" :: "r"(dst), "l"(src) : "memory")
#define CPCOMMIT() asm volatile("cp.async.commit_group;" ::: "memory")

__device__ __forceinline__ uint32_t smem_u32(const void* p) {
    uint32_t a;
    asm("{ .reg .u64 t; cvta.to.shared.u64 t, %1; cvt.u32.u64 %0, t; }" : "=r"(a) : "l"(p));
    return a;
}

// ---------------- kernel 1: pre-convert fp32 -> bf16 hi (+ zero counters) ----------
#define BGROUPS (KQ * 16)
#define AGROUPS (NQ * 16)

__global__ void __launch_bounds__(256)
convert_kernel(const float* __restrict__ A, const float* __restrict__ B) {
    int t = blockIdx.x * 256 + threadIdx.x;
    if (t < NQ) g_cnt[t] = 0;
    if (t == 0) g_correct = 0;

    const float* src;
    uint32_t* dh;
    if (t < BGROUPS) {
        int row = t >> 4, k16 = t & 15;
        src = B + (size_t)row * DIM + k16 * 16;
        size_t g = ((size_t)(row >> 7) * 16 + k16) * 128 + (row & 127);
        dh = g_Bh + g * 8;
    } else if (t < BGROUPS + AGROUPS) {
        int u = t - BGROUPS;
        int row = u >> 4, k16 = u & 15;
        src = A + (size_t)row * DIM + k16 * 16;
        size_t g = ((size_t)(row >> 7) * 16 + k16) * 128 + (row & 127);
        dh = g_Ah + g * 8;
    } else return;

    float e[16];
    #pragma unroll
    for (int i = 0; i < 4; i++) {
        float4 v = *(const float4*)(src + i * 4);
        e[i*4+0] = v.x; e[i*4+1] = v.y; e[i*4+2] = v.z; e[i*4+3] = v.w;
    }
    uint32_t h[8];
    #pragma unroll
    for (int q = 0; q < 8; q++) {
        int p = ((q & 3) << 1) | (q >> 2);
        __nv_bfloat162 hh = __floats2bfloat162_rn(e[2*q], e[2*q+1]);
        h[p] = *(uint32_t*)&hh;
    }
    *(uint4*)(dh)     = make_uint4(h[0], h[1], h[2], h[3]);
    *(uint4*)(dh + 4) = make_uint4(h[4], h[5], h[6], h[7]);
}

// ---------------- kernel 2: 1-pass coarse HMMA GEMM -> survivor indices -----------
#define TM 128
#define TN 128
#define NCHUNK 8
#define STAGE_W 4096
#define GEMM_SMEM (2 * STAGE_W * 4)

__device__ __forceinline__ void mma16816(float* c, const uint32_t* a, const uint32_t* b) {
    asm volatile(
        "mma.sync.aligned.m16n8k16.row.col.f32.bf16.bf16.f32 "
        "{%0,%1,%2,%3}, {%4,%5,%6,%7}, {%8,%9}, {%0,%1,%2,%3};"
        : "+f"(c[0]), "+f"(c[1]), "+f"(c[2]), "+f"(c[3])
        : "r"(a[0]), "r"(a[1]), "r"(a[2]), "r"(a[3]), "r"(b[0]), "r"(b[1]));
}

__device__ __forceinline__ void cappend_idx(int qrow, float v, int col) {
    if (v > T_COARSE) {
        int slot = atomicAdd(&g_cnt[qrow], 1);
        if (slot < CMAX) g_cidx[(size_t)qrow * CMAX + slot] = (unsigned)col;
    }
}

__global__ void __launch_bounds__(256, 2)
gemm_tc_kernel() {
    extern __shared__ uint32_t smw[];
    const uint32_t sb = smem_u32(smw);
    const int tid  = threadIdx.x;
    const int lane = tid & 31;
    const int wid  = tid >> 5;
    const int gID  = lane >> 2;
    const int tig  = lane & 3;
    const int wm   = wid >> 2;
    const int wn   = wid & 3;
    const int m_t  = blockIdx.x;     // 0..3 (fast -> B tile L2 reuse)
    const int n_t  = blockIdx.y;     // 0..511

    float acc[4][4][4];
    #pragma unroll
    for (int m = 0; m < 4; m++)
        #pragma unroll
        for (int n = 0; n < 4; n++)
            #pragma unroll
            for (int r = 0; r < 4; r++) acc[m][n][r] = 0.f;

    const uint32_t* srcA = g_Ah + ((size_t)m_t * 16) * 1024;
    const uint32_t* srcB = g_Bh + ((size_t)n_t * 16) * 1024;

    auto stage = [&](int ch, int buf) {
        uint32_t d0 = sb + buf * (STAGE_W * 4);
        size_t goff = (size_t)(2 * ch) * 1024;
        const uint32_t* s[2] = { srcA + goff, srcB + goff };
        #pragma unroll
        for (int tl = 0; tl < 2; tl++) {
            uint32_t d = d0 + tl * 8192 + tid * 16;
            const char* sp = (const char*)s[tl] + tid * 16;
            CP16(d, sp);
            CP16(d + 4096, sp + 4096);
        }
    };

    stage(0, 0); CPCOMMIT();
    stage(1, 1); CPCOMMIT();

    for (int ch = 0; ch < NCHUNK; ++ch) {
        asm volatile("cp.async.wait_group 1;" ::: "memory");
        __syncthreads();

        const uint32_t* Ah = smw + (ch & 1) * STAGE_W;
        const uint32_t* Bh = Ah + 2048;

        #pragma unroll
        for (int s = 0; s < 2; s++) {
            uint32_t afr[4][4];
            #pragma unroll
            for (int m = 0; m < 4; m++) {
                int row = wm * 64 + m * 16 + gID;
                uint2 v0 = *(const uint2*)(Ah + (s * 128 + row) * 8 + tig * 2);
                uint2 v1 = *(const uint2*)(Ah + (s * 128 + row + 8) * 8 + tig * 2);
                afr[m][0] = v0.x; afr[m][2] = v0.y;
                afr[m][1] = v1.x; afr[m][3] = v1.y;
            }
            uint32_t bfr[4][2];
            #pragma unroll
            for (int n = 0; n < 4; n++) {
                int rowb = wn * 32 + n * 8 + gID;
                uint2 v = *(const uint2*)(Bh + (s * 128 + rowb) * 8 + tig * 2);
                bfr[n][0] = v.x; bfr[n][1] = v.y;
            }
            #pragma unroll
            for (int m = 0; m < 4; m++)
                #pragma unroll
                for (int n = 0; n < 4; n++)
                    mma16816(acc[m][n], afr[m], bfr[n]);
        }
        __syncthreads();

        if (ch + 2 < NCHUNK) stage(ch + 2, ch & 1);
        CPCOMMIT();
    }

    #pragma unroll
    for (int m = 0; m < 4; m++) {
        int row = m_t * TM + wm * 64 + m * 16 + gID;
        #pragma unroll
        for (int n = 0; n < 4; n++) {
            int col = n_t * TN + wn * 32 + n * 8 + tig * 2;
            cappend_idx(row,     acc[m][n][0], col);
            cappend_idx(row,     acc[m][n][1], col + 1);
            cappend_idx(row + 8, acc[m][n][2], col);
            cappend_idx(row + 8, acc[m][n][3], col + 1);
        }
    }
}

// ---------------- kernel 3: exact fp32 rescue of survivors (2-way ILP) ----------------
__global__ void __launch_bounds__(256)
rescue_kernel(const float* __restrict__ feats, const float* __restrict__ qf) {
    __shared__ float fvec[DIM];
    const int tid  = threadIdx.x;
    const int lane = tid & 31;
    const int wid  = tid >> 5;
    const int q    = blockIdx.x;
    const int cnt  = min(g_cnt[q], CMAX);

    for (int i = tid; i < DIM; i += 256) fvec[i] = feats[(size_t)q * DIM + i];
    __syncthreads();

    float a0 = fvec[lane * 8 + 0], a1 = fvec[lane * 8 + 1],
          a2 = fvec[lane * 8 + 2], a3 = fvec[lane * 8 + 3],
          a4 = fvec[lane * 8 + 4], a5 = fvec[lane * 8 + 5],
          a6 = fvec[lane * 8 + 6], a7 = fvec[lane * 8 + 7];

    for (int c = wid; c < cnt; c += 16) {
        int c2 = c + 8;
        bool have2 = (c2 < cnt);
        unsigned idx1 = g_cidx[(size_t)q * CMAX + c];
        unsigned idx2 = have2 ? g_cidx[(size_t)q * CMAX + c2] : idx1;

        const float4* p4 = (const float4*)(qf + (size_t)idx1 * DIM) + lane * 2;
        const float4* r4 = (const float4*)(qf + (size_t)idx2 * DIM) + lane * 2;
        float4 p0 = p4[0], p1 = p4[1];
        float4 r0 = r4[0], r1 = r4[1];

        float d1 = a0 * p0.x;
        float d2 = a0 * r0.x;
        d1 = fmaf(a1, p0.y, d1);  d2 = fmaf(a1, r0.y, d2);
        d1 = fmaf(a2, p0.z, d1);  d2 = fmaf(a2, r0.z, d2);
        d1 = fmaf(a3, p0.w, d1);  d2 = fmaf(a3, r0.w, d2);
        d1 = fmaf(a4, p1.x, d1);  d2 = fmaf(a4, r1.x, d2);
        d1 = fmaf(a5, p1.y, d1);  d2 = fmaf(a5, r1.y, d2);
        d1 = fmaf(a6, p1.z, d1);  d2 = fmaf(a6, r1.z, d2);
        d1 = fmaf(a7, p1.w, d1);  d2 = fmaf(a7, r1.w, d2);

        #pragma unroll
        for (int o = 16; o > 0; o >>= 1) {
            d1 += __shfl_xor_sync(0xFFFFFFFFu, d1, o);
            d2 += __shfl_xor_sync(0xFFFFFFFFu, d2, o);
        }
        if (lane == 0) {
            g_cand[(size_t)q * CMAX + c] =
                ((unsigned long long)__float_as_uint(d1) << 32) |
                (unsigned)(idx1 ^ 0xFFFFu);
            if (have2)
                g_cand[(size_t)q * CMAX + c2] =
                    ((unsigned long long)__float_as_uint(d2) << 32) |
                    (unsigned)(idx2 ^ 0xFFFFu);
        }
    }
}

// ---------------- kernel 4: top-200 + vote + argmax (guarded fast path) ----------------
#define TK_BINS 2048
#define BND_MAX 1024
#define TOPK_SMEM (32768 + 8192 + 4096)

__device__ __forceinline__ int val_bin(unsigned bits) {
    if (bits <= 0x3E000000u) return 0;
    unsigned b = (bits - 0x3E000000u) >> 14;
    return (b > TK_BINS - 1) ? (TK_BINS - 1) : (int)b;
}

__global__ void __launch_bounds__(256)
topk_kernel(const int* __restrict__ qlabels, const int* __restrict__ labels,
            const float* __restrict__ feats, const float* __restrict__ qf) {
    extern __shared__ char smem[];
    unsigned long long* cand = (unsigned long long*)smem;
    unsigned* hist = (unsigned*)(smem + 32768);
    float* scores  = (float*)(smem + 32768 + 8192);

    __shared__ unsigned long long bnd[BND_MAX];
    __shared__ unsigned s_gsum[256];
    __shared__ int s_B, s_cGreater, s_bcnt;
    __shared__ float s_bv[256];
    __shared__ int   s_bi[256];

    const int tid = threadIdx.x;
    const int q   = blockIdx.x;
    const int cnt = g_cnt[q];
    bool fast = (cnt >= KNN && cnt <= CMAX);
    bool row_built = false;

    for (int i = tid; i < 1024; i += 256) scores[i] = 0.f;
    if (fast) {
        for (int i = tid; i < cnt; i += 256)
            cand[i] = g_cand[(size_t)q * CMAX + i];
    }

    int B, need;
    while (true) {
        for (int i = tid; i < TK_BINS; i += 256) hist[i] = 0u;
        if (tid == 0) s_bcnt = 0;
        __syncthreads();

        if (fast) {
            for (int i = tid; i < cnt; i += 256)
                atomicAdd(&hist[val_bin((unsigned)(cand[i] >> 32))], 1u);
        } else {
            if (!row_built) {
                float* fvec = (float*)bnd;
                for (int i = tid; i < DIM; i += 256) fvec[i] = feats[(size_t)q * DIM + i];
                __syncthreads();
                float* row = g_sim + (size_t)q * KQ;
                for (int i = tid; i < KQ; i += 256) {
                    const float4* b4 = (const float4*)(qf + (size_t)i * DIM);
                    float d = 0.f;
                    #pragma unroll 8
                    for (int k = 0; k < DIM / 4; k++) {
                        float4 bv = b4[k];
                        d = fmaf(fvec[4*k+0], bv.x, d);
                        d = fmaf(fvec[4*k+1], bv.y, d);
                        d = fmaf(fvec[4*k+2], bv.z, d);
                        d = fmaf(fvec[4*k+3], bv.w, d);
                    }
                    row[i] = d;
                }
                row_built = true;
                __syncthreads();
            }
            const float* row = g_sim + (size_t)q * KQ;
            for (int i = tid; i < KQ; i += 256)
                atomicAdd(&hist[orderf(row[i]) >> 21], 1u);
        }
        __syncthreads();

        unsigned gs = 0;
        #pragma unroll 8
        for (int b = 0; b < 8; b++) gs += hist[tid * 8 + b];
        s_gsum[tid] = gs;
        __syncthreads();

        if (tid == 0) {
            unsigned cum = 0; int Bl = 0; unsigned cG = 0;
            for (int g = 255; g >= 0; --g) {
                if (cum + s_gsum[g] >= KNN) {
                    for (int b = g * 8 + 7; b >= g * 8; --b) {
                        if (cum + hist[b] >= KNN) { Bl = b; cG = cum; break; }
                        cum += hist[b];
                    }
                    break;
                }
                cum += s_gsum[g];
            }
            s_B = Bl; s_cGreater = (int)cG;
        }
        __syncthreads();
        B = s_B; need = KNN - s_cGreater;

        if (fast) {
            float blow = __uint_as_float(0x3E000000u + ((unsigned)B << 14));
            if (blow < T_SAFE) { fast = false; __syncthreads(); continue; }
        }
        break;
    }

    if (fast) {
        for (int i = tid; i < cnt; i += 256) {
            unsigned long long c = cand[i];
            unsigned bits = (unsigned)(c >> 32);
            int bin = val_bin(bits);
            if (bin > B) {
                int idx = ((int)((unsigned)c & 0xFFFFu)) ^ 0xFFFF;
                atomicAdd(&scores[qlabels[idx]], expf(__uint_as_float(bits) * INVT));
            } else if (bin == B) {
                int p = atomicAdd(&s_bcnt, 1);
                if (p < BND_MAX) bnd[p] = c;
            }
        }
    } else {
        const float* row = g_sim + (size_t)q * KQ;
        for (int i = tid; i < KQ; i += 256) {
            float v = row[i];
            unsigned k = orderf(v);
            int bin = (int)(k >> 21);
            if (bin > B) {
                atomicAdd(&scores[qlabels[i]], expf(v * INVT));
            } else if (bin == B) {
                int p = atomicAdd(&s_bcnt, 1);
                if (p < BND_MAX)
                    bnd[p] = ((unsigned long long)k << 32) | (unsigned)(i ^ 0xFFFF);
            }
        }
    }
    __syncthreads();

    int bcnt = min(s_bcnt, BND_MAX);
    if (need > bcnt) need = bcnt;
    for (int i = tid; i < bcnt; i += 256) {
        unsigned long long mine = bnd[i];
        int rank = 0;
        for (int j = 0; j < bcnt; j++) rank += (bnd[j] > mine);
        if (rank < need) {
            unsigned hi = (unsigned)(mine >> 32);
            float v = fast ? __uint_as_float(hi) : unorderf(hi);
            int idx = ((int)((unsigned)mine & 0xFFFFu)) ^ 0xFFFF;
            atomicAdd(&scores[qlabels[idx]], expf(v * INVT));
        }
    }
    __syncthreads();

    float best = -1.f; int bi = NCLS;
    for (int c = tid; c < NCLS; c += 256) {
        float v = scores[c];
        if (v > best) { best = v; bi = c; }
    }
    s_bv[tid] = best; s_bi[tid] = bi;
    __syncthreads();
    for (int s = 128; s > 0; s >>= 1) {
        if (tid < s) {
            float ov = s_bv[tid + s]; int oi = s_bi[tid + s];
            if (ov > s_bv[tid] || (ov == s_bv[tid] && oi < s_bi[tid])) {
                s_bv[tid] = ov; s_bi[tid] = oi;
            }
        }
        __syncthreads();
    }
    if (tid == 0 && s_bi[0] == labels[q]) atomicAdd(&g_correct, 1);
}

// ---------------- kernel 5: queue update copy (no scalars; may run concurrently) -------
__global__ void __launch_bounds__(256)
copy_kernel(const float* __restrict__ feats, const int* __restrict__ labels,
            const float* __restrict__ qf, const int* __restrict__ ql,
            const int* __restrict__ qptr, float* __restrict__ out) {
    const int ptr = qptr[0];
    size_t i4 = (size_t)blockIdx.x * 256 + threadIdx.x;
    if (i4 < (size_t)(NF / 4)) {
        int r = (int)(i4 >> 6);
        int rel = r - ptr; if (rel < 0) rel += KQ;
        float4 v = (rel < NQ) ? ((const float4*)feats)[(size_t)rel * 64 + (i4 & 63)]
                              : ((const float4*)qf)[i4];
        float* o = out + OUT_FEAT_OFF + i4 * 4;
        o[0] = v.x; o[1] = v.y; o[2] = v.z; o[3] = v.w;
    } else if (i4 < (size_t)(NF / 4 + NL / 4)) {
        int j4 = (int)(i4 - NF / 4);
        int4 lv = ((const int4*)ql)[j4];
        int base = j4 * 4;
        float* o = out + OUT_LAB_OFF + base;
        #pragma unroll
        for (int k = 0; k < 4; k++) {
            int i = base + k;
            int rel = i - ptr; if (rel < 0) rel += KQ;
            int lab = (rel < NQ) ? labels[rel] : ((const int*)&lv)[k];
            o[k] = (float)lab;
        }
    }
}

// ---------------- kernel 6: scalars (after topk) ----------------
__global__ void finalize_kernel(const int* __restrict__ qptr, float* __restrict__ out) {
    out[0] = (float)g_correct * (1.0f / (float)NQ);
    out[OUT_PTR_OFF] = (float)((qptr[0] + NQ) % KQ);
}

// ---------------- launch ----------------
extern "C" void kernel_launch(void* const* d_in, const int* in_sizes, int n_in,
                              void* d_out, int out_size) {
    const float* feats  = (const float*)d_in[0];
    const int*   labels = (const int*)d_in[1];
    const float* qf     = (const float*)d_in[2];
    const int*   ql     = (const int*)d_in[3];
    const int*   qptr   = (const int*)d_in[4];
    float* out = (float*)d_out;

    cudaFuncSetAttribute(gemm_tc_kernel, cudaFuncAttributeMaxDynamicSharedMemorySize, GEMM_SMEM);
    cudaFuncSetAttribute(topk_kernel, cudaFuncAttributeMaxDynamicSharedMemorySize, TOPK_SMEM);

    // lazy one-time side-stream setup (host objects only; no device memory)
    static cudaStream_t s2 = nullptr;
    static cudaEvent_t evF = nullptr, evJ = nullptr;
    static bool tried = false;
    if (!tried) {
        tried = true;
        if (cudaStreamCreateWithFlags(&s2, cudaStreamNonBlocking) != cudaSuccess) s2 = nullptr;
        if (s2) {
            if (cudaEventCreateWithFlags(&evF, cudaEventDisableTiming) != cudaSuccess ||
                cudaEventCreateWithFlags(&evJ, cudaEventDisableTiming) != cudaSuccess) {
                s2 = nullptr;
            }
        }
    }

    int total4 = NF / 4 + NL / 4;
    int copy_blocks = (total4 + 255) / 256;

    if (s2) {
        // fork: copy depends only on inputs -> run concurrently with the pipeline
        cudaEventRecord(evF, 0);
        cudaStreamWaitEvent(s2, evF, 0);
        copy_kernel<<<copy_blocks, 256, 0, s2>>>(feats, labels, qf, ql, qptr, out);
        cudaEventRecord(evJ, s2);
    }

    convert_kernel<<<(BGROUPS + AGROUPS + 255) / 256, 256>>>(feats, qf);
    gemm_tc_kernel<<<dim3(NQ / TM, KQ / TN), 256, GEMM_SMEM>>>();
    rescue_kernel<<<NQ, 256>>>(feats, qf);
    topk_kernel<<<NQ, 256, TOPK_SMEM>>>(ql, labels, feats, qf);

    if (s2) {
        cudaStreamWaitEvent(0, evJ, 0);     // join before final scalar write
    } else {
        copy_kernel<<<copy_blocks, 256>>>(feats, labels, qf, ql, qptr, out);
    }
    finalize_kernel<<<1, 1>>>(qptr, out);
    (void)in_sizes; (void)n_in; (void)out_size;
}

// round 15
// speedup vs baseline: 1.4755x; 1.0168x over previous
#include <cuda_runtime.h>
#include <cuda_bf16.h>
#include <math.h>
#include <cstdint>

// ---------------- problem constants ----------------
#define NQ      512
#define DIM     256
#define KQ      65536
#define KNN     200
#define NCLS    1000
#define INVT    (1.0f/0.07f)

#define NF      (KQ*DIM)
#define NL      KQ

#define OUT_FEAT_OFF 1
#define OUT_LAB_OFF  (1 + NF)
#define OUT_PTR_OFF  (1 + NF + NL)

// candidate filtering
#define CMAX        4096
#define T_COARSE    0.160f    // coarse (hi*hi) filter threshold
#define T_SAFE      0.1633f   // fast path valid iff 200th exact value >= this

#define RESCUE_SPLIT 4        // blocks per query in rescue

// ---------------- device scratch ----------------
__device__ float g_sim[(size_t)NQ * KQ];                 // fallback scratch only
__device__ unsigned g_cidx[(size_t)NQ * CMAX];           // coarse survivor indices
__device__ unsigned long long g_cand[(size_t)NQ * CMAX]; // exact (val,idx) records
__device__ int  g_cnt[NQ];
__device__ int  g_correct;
__device__ int  g_done;

// pre-converted bf16 hi operands, tile-sequential permuted layout
__device__ uint32_t g_Ah[65536];
__device__ uint32_t g_Bh[(size_t)8388608];

__device__ __forceinline__ unsigned orderf(float f) {
    unsigned u = __float_as_uint(f);
    return (u & 0x80000000u) ? ~u : (u | 0x80000000u);
}
__device__ __forceinline__ float unorderf(unsigned k) {
    return __uint_as_float((k & 0x80000000u) ? (k ^ 0x80000000u) : ~k);
}

#define CP16(dst, src) \
    asm volatile("cp.async.cg.shared.global [%0], [%1], 16;" :: "r"(dst), "l"(src) : "memory")
#define CPCOMMIT() asm volatile("cp.async.commit_group;" ::: "memory")

__device__ __forceinline__ uint32_t smem_u32(const void* p) {
    uint32_t a;
    asm("{ .reg .u64 t; cvta.to.shared.u64 t, %1; cvt.u32.u64 %0, t; }" : "=r"(a) : "l"(p));
    return a;
}

// ---------------- kernel 1: pre-convert fp32 -> bf16 hi (+ zero counters) ----------
#define BGROUPS (KQ * 16)
#define AGROUPS (NQ * 16)

__global__ void __launch_bounds__(256)
convert_kernel(const float* __restrict__ A, const float* __restrict__ B) {
    int t = blockIdx.x * 256 + threadIdx.x;
    if (t < NQ) g_cnt[t] = 0;
    if (t == 0) { g_correct = 0; g_done = 0; }

    const float* src;
    uint32_t* dh;
    if (t < BGROUPS) {
        int row = t >> 4, k16 = t & 15;
        src = B + (size_t)row * DIM + k16 * 16;
        size_t g = ((size_t)(row >> 7) * 16 + k16) * 128 + (row & 127);
        dh = g_Bh + g * 8;
    } else if (t < BGROUPS + AGROUPS) {
        int u = t - BGROUPS;
        int row = u >> 4, k16 = u & 15;
        src = A + (size_t)row * DIM + k16 * 16;
        size_t g = ((size_t)(row >> 7) * 16 + k16) * 128 + (row & 127);
        dh = g_Ah + g * 8;
    } else return;

    float e[16];
    #pragma unroll
    for (int i = 0; i < 4; i++) {
        float4 v = *(const float4*)(src + i * 4);
        e[i*4+0] = v.x; e[i*4+1] = v.y; e[i*4+2] = v.z; e[i*4+3] = v.w;
    }
    uint32_t h[8];
    #pragma unroll
    for (int q = 0; q < 8; q++) {
        int p = ((q & 3) << 1) | (q >> 2);
        __nv_bfloat162 hh = __floats2bfloat162_rn(e[2*q], e[2*q+1]);
        h[p] = *(uint32_t*)&hh;
    }
    *(uint4*)(dh)     = make_uint4(h[0], h[1], h[2], h[3]);
    *(uint4*)(dh + 4) = make_uint4(h[4], h[5], h[6], h[7]);
}

// ---------------- kernel 2: 1-pass coarse HMMA GEMM -> survivor indices -----------
#define TM 128
#define TN 128
#define NCHUNK 8
#define STAGE_W 4096
#define GEMM_SMEM (2 * STAGE_W * 4)

__device__ __forceinline__ void mma16816(float* c, const uint32_t* a, const uint32_t* b) {
    asm volatile(
        "mma.sync.aligned.m16n8k16.row.col.f32.bf16.bf16.f32 "
        "{%0,%1,%2,%3}, {%4,%5,%6,%7}, {%8,%9}, {%0,%1,%2,%3};"
        : "+f"(c[0]), "+f"(c[1]), "+f"(c[2]), "+f"(c[3])
        : "r"(a[0]), "r"(a[1]), "r"(a[2]), "r"(a[3]), "r"(b[0]), "r"(b[1]));
}

__device__ __forceinline__ void cappend_idx(int qrow, float v, int col) {
    if (v > T_COARSE) {
        int slot = atomicAdd(&g_cnt[qrow], 1);
        if (slot < CMAX) g_cidx[(size_t)qrow * CMAX + slot] = (unsigned)col;
    }
}

__global__ void __launch_bounds__(256, 2)
gemm_tc_kernel() {
    extern __shared__ uint32_t smw[];
    const uint32_t sb = smem_u32(smw);
    const int tid  = threadIdx.x;
    const int lane = tid & 31;
    const int wid  = tid >> 5;
    const int gID  = lane >> 2;
    const int tig  = lane & 3;
    const int wm   = wid >> 2;
    const int wn   = wid & 3;
    const int m_t  = blockIdx.x;     // 0..3 (fast -> B tile L2 reuse)
    const int n_t  = blockIdx.y;     // 0..511

    float acc[4][4][4];
    #pragma unroll
    for (int m = 0; m < 4; m++)
        #pragma unroll
        for (int n = 0; n < 4; n++)
            #pragma unroll
            for (int r = 0; r < 4; r++) acc[m][n][r] = 0.f;

    const uint32_t* srcA = g_Ah + ((size_t)m_t * 16) * 1024;
    const uint32_t* srcB = g_Bh + ((size_t)n_t * 16) * 1024;

    auto stage = [&](int ch, int buf) {
        uint32_t d0 = sb + buf * (STAGE_W * 4);
        size_t goff = (size_t)(2 * ch) * 1024;
        const uint32_t* s[2] = { srcA + goff, srcB + goff };
        #pragma unroll
        for (int tl = 0; tl < 2; tl++) {
            uint32_t d = d0 + tl * 8192 + tid * 16;
            const char* sp = (const char*)s[tl] + tid * 16;
            CP16(d, sp);
            CP16(d + 4096, sp + 4096);
        }
    };

    stage(0, 0); CPCOMMIT();
    stage(1, 1); CPCOMMIT();

    for (int ch = 0; ch < NCHUNK; ++ch) {
        asm volatile("cp.async.wait_group 1;" ::: "memory");
        __syncthreads();

        const uint32_t* Ah = smw + (ch & 1) * STAGE_W;
        const uint32_t* Bh = Ah + 2048;

        #pragma unroll
        for (int s = 0; s < 2; s++) {
            uint32_t afr[4][4];
            #pragma unroll
            for (int m = 0; m < 4; m++) {
                int row = wm * 64 + m * 16 + gID;
                uint2 v0 = *(const uint2*)(Ah + (s * 128 + row) * 8 + tig * 2);
                uint2 v1 = *(const uint2*)(Ah + (s * 128 + row + 8) * 8 + tig * 2);
                afr[m][0] = v0.x; afr[m][2] = v0.y;
                afr[m][1] = v1.x; afr[m][3] = v1.y;
            }
            uint32_t bfr[4][2];
            #pragma unroll
            for (int n = 0; n < 4; n++) {
                int rowb = wn * 32 + n * 8 + gID;
                uint2 v = *(const uint2*)(Bh + (s * 128 + rowb) * 8 + tig * 2);
                bfr[n][0] = v.x; bfr[n][1] = v.y;
            }
            #pragma unroll
            for (int m = 0; m < 4; m++)
                #pragma unroll
                for (int n = 0; n < 4; n++)
                    mma16816(acc[m][n], afr[m], bfr[n]);
        }
        __syncthreads();

        if (ch + 2 < NCHUNK) stage(ch + 2, ch & 1);
        CPCOMMIT();
    }

    #pragma unroll
    for (int m = 0; m < 4; m++) {
        int row = m_t * TM + wm * 64 + m * 16 + gID;
        #pragma unroll
        for (int n = 0; n < 4; n++) {
            int col = n_t * TN + wn * 32 + n * 8 + tig * 2;
            cappend_idx(row,     acc[m][n][0], col);
            cappend_idx(row,     acc[m][n][1], col + 1);
            cappend_idx(row + 8, acc[m][n][2], col);
            cappend_idx(row + 8, acc[m][n][3], col + 1);
        }
    }
}

// ---------------- kernel 3: exact fp32 rescue (4 blocks/query, 2-way ILP) -------------
__global__ void __launch_bounds__(256)
rescue_kernel(const float* __restrict__ feats, const float* __restrict__ qf) {
    __shared__ float fvec[DIM];
    const int tid  = threadIdx.x;
    const int lane = tid & 31;
    const int wid  = tid >> 5;
    const int q    = blockIdx.x >> 2;          // 4 blocks per query
    const int part = blockIdx.x & 3;
    const int cnt  = min(g_cnt[q], CMAX);

    // this block's slice [lo, hi)
    const int step = (cnt + RESCUE_SPLIT - 1) / RESCUE_SPLIT;
    const int lo = part * step;
    const int hi = min(lo + step, cnt);
    if (lo >= hi) return;

    for (int i = tid; i < DIM; i += 256) fvec[i] = feats[(size_t)q * DIM + i];
    __syncthreads();

    float a0 = fvec[lane * 8 + 0], a1 = fvec[lane * 8 + 1],
          a2 = fvec[lane * 8 + 2], a3 = fvec[lane * 8 + 3],
          a4 = fvec[lane * 8 + 4], a5 = fvec[lane * 8 + 5],
          a6 = fvec[lane * 8 + 6], a7 = fvec[lane * 8 + 7];

    for (int c = lo + wid; c < hi; c += 16) {
        int c2 = c + 8;
        bool have2 = (c2 < hi);
        unsigned idx1 = g_cidx[(size_t)q * CMAX + c];
        unsigned idx2 = have2 ? g_cidx[(size_t)q * CMAX + c2] : idx1;

        const float4* p4 = (const float4*)(qf + (size_t)idx1 * DIM) + lane * 2;
        const float4* r4 = (const float4*)(qf + (size_t)idx2 * DIM) + lane * 2;
        float4 p0 = p4[0], p1 = p4[1];
        float4 r0 = r4[0], r1 = r4[1];

        float d1 = a0 * p0.x;
        float d2 = a0 * r0.x;
        d1 = fmaf(a1, p0.y, d1);  d2 = fmaf(a1, r0.y, d2);
        d1 = fmaf(a2, p0.z, d1);  d2 = fmaf(a2, r0.z, d2);
        d1 = fmaf(a3, p0.w, d1);  d2 = fmaf(a3, r0.w, d2);
        d1 = fmaf(a4, p1.x, d1);  d2 = fmaf(a4, r1.x, d2);
        d1 = fmaf(a5, p1.y, d1);  d2 = fmaf(a5, r1.y, d2);
        d1 = fmaf(a6, p1.z, d1);  d2 = fmaf(a6, r1.z, d2);
        d1 = fmaf(a7, p1.w, d1);  d2 = fmaf(a7, r1.w, d2);

        #pragma unroll
        for (int o = 16; o > 0; o >>= 1) {
            d1 += __shfl_xor_sync(0xFFFFFFFFu, d1, o);
            d2 += __shfl_xor_sync(0xFFFFFFFFu, d2, o);
        }
        if (lane == 0) {
            g_cand[(size_t)q * CMAX + c] =
                ((unsigned long long)__float_as_uint(d1) << 32) |
                (unsigned)(idx1 ^ 0xFFFFu);
            if (have2)
                g_cand[(size_t)q * CMAX + c2] =
                    ((unsigned long long)__float_as_uint(d2) << 32) |
                    (unsigned)(idx2 ^ 0xFFFFu);
        }
    }
}

// ---------------- kernel 4: top-200 + vote + argmax (+ last block writes scalars) ------
#define TK_BINS 2048
#define BND_MAX 1024
#define TOPK_SMEM (32768 + 8192 + 4096)

__device__ __forceinline__ int val_bin(unsigned bits) {
    if (bits <= 0x3E000000u) return 0;
    unsigned b = (bits - 0x3E000000u) >> 14;
    return (b > TK_BINS - 1) ? (TK_BINS - 1) : (int)b;
}

__global__ void __launch_bounds__(256)
topk_kernel(const int* __restrict__ qlabels, const int* __restrict__ labels,
            const float* __restrict__ feats, const float* __restrict__ qf,
            const int* __restrict__ qptr, float* __restrict__ out) {
    extern __shared__ char smem[];
    unsigned long long* cand = (unsigned long long*)smem;
    unsigned* hist = (unsigned*)(smem + 32768);
    float* scores  = (float*)(smem + 32768 + 8192);

    __shared__ unsigned long long bnd[BND_MAX];
    __shared__ unsigned s_gsum[256];
    __shared__ int s_B, s_cGreater, s_bcnt;
    __shared__ float s_bv[256];
    __shared__ int   s_bi[256];

    const int tid = threadIdx.x;
    const int q   = blockIdx.x;
    const int cnt = g_cnt[q];
    bool fast = (cnt >= KNN && cnt <= CMAX);
    bool row_built = false;

    for (int i = tid; i < 1024; i += 256) scores[i] = 0.f;
    if (fast) {
        for (int i = tid; i < cnt; i += 256)
            cand[i] = g_cand[(size_t)q * CMAX + i];
    }

    int B, need;
    while (true) {
        for (int i = tid; i < TK_BINS; i += 256) hist[i] = 0u;
        if (tid == 0) s_bcnt = 0;
        __syncthreads();

        if (fast) {
            for (int i = tid; i < cnt; i += 256)
                atomicAdd(&hist[val_bin((unsigned)(cand[i] >> 32))], 1u);
        } else {
            if (!row_built) {
                float* fvec = (float*)bnd;
                for (int i = tid; i < DIM; i += 256) fvec[i] = feats[(size_t)q * DIM + i];
                __syncthreads();
                float* row = g_sim + (size_t)q * KQ;
                for (int i = tid; i < KQ; i += 256) {
                    const float4* b4 = (const float4*)(qf + (size_t)i * DIM);
                    float d = 0.f;
                    #pragma unroll 8
                    for (int k = 0; k < DIM / 4; k++) {
                        float4 bv = b4[k];
                        d = fmaf(fvec[4*k+0], bv.x, d);
                        d = fmaf(fvec[4*k+1], bv.y, d);
                        d = fmaf(fvec[4*k+2], bv.z, d);
                        d = fmaf(fvec[4*k+3], bv.w, d);
                    }
                    row[i] = d;
                }
                row_built = true;
                __syncthreads();
            }
            const float* row = g_sim + (size_t)q * KQ;
            for (int i = tid; i < KQ; i += 256)
                atomicAdd(&hist[orderf(row[i]) >> 21], 1u);
        }
        __syncthreads();

        unsigned gs = 0;
        #pragma unroll 8
        for (int b = 0; b < 8; b++) gs += hist[tid * 8 + b];
        s_gsum[tid] = gs;
        __syncthreads();

        if (tid == 0) {
            unsigned cum = 0; int Bl = 0; unsigned cG = 0;
            for (int g = 255; g >= 0; --g) {
                if (cum + s_gsum[g] >= KNN) {
                    for (int b = g * 8 + 7; b >= g * 8; --b) {
                        if (cum + hist[b] >= KNN) { Bl = b; cG = cum; break; }
                        cum += hist[b];
                    }
                    break;
                }
                cum += s_gsum[g];
            }
            s_B = Bl; s_cGreater = (int)cG;
        }
        __syncthreads();
        B = s_B; need = KNN - s_cGreater;

        if (fast) {
            float blow = __uint_as_float(0x3E000000u + ((unsigned)B << 14));
            if (blow < T_SAFE) { fast = false; __syncthreads(); continue; }
        }
        break;
    }

    if (fast) {
        for (int i = tid; i < cnt; i += 256) {
            unsigned long long c = cand[i];
            unsigned bits = (unsigned)(c >> 32);
            int bin = val_bin(bits);
            if (bin > B) {
                int idx = ((int)((unsigned)c & 0xFFFFu)) ^ 0xFFFF;
                atomicAdd(&scores[qlabels[idx]], expf(__uint_as_float(bits) * INVT));
            } else if (bin == B) {
                int p = atomicAdd(&s_bcnt, 1);
                if (p < BND_MAX) bnd[p] = c;
            }
        }
    } else {
        const float* row = g_sim + (size_t)q * KQ;
        for (int i = tid; i < KQ; i += 256) {
            float v = row[i];
            unsigned k = orderf(v);
            int bin = (int)(k >> 21);
            if (bin > B) {
                atomicAdd(&scores[qlabels[i]], expf(v * INVT));
            } else if (bin == B) {
                int p = atomicAdd(&s_bcnt, 1);
                if (p < BND_MAX)
                    bnd[p] = ((unsigned long long)k << 32) | (unsigned)(i ^ 0xFFFF);
            }
        }
    }
    __syncthreads();

    int bcnt = min(s_bcnt, BND_MAX);
    if (need > bcnt) need = bcnt;
    for (int i = tid; i < bcnt; i += 256) {
        unsigned long long mine = bnd[i];
        int rank = 0;
        for (int j = 0; j < bcnt; j++) rank += (bnd[j] > mine);
        if (rank < need) {
            unsigned hi = (unsigned)(mine >> 32);
            float v = fast ? __uint_as_float(hi) : unorderf(hi);
            int idx = ((int)((unsigned)mine & 0xFFFFu)) ^ 0xFFFF;
            atomicAdd(&scores[qlabels[idx]], expf(v * INVT));
        }
    }
    __syncthreads();

    float best = -1.f; int bi = NCLS;
    for (int c = tid; c < NCLS; c += 256) {
        float v = scores[c];
        if (v > best) { best = v; bi = c; }
    }
    s_bv[tid] = best; s_bi[tid] = bi;
    __syncthreads();
    for (int s = 128; s > 0; s >>= 1) {
        if (tid < s) {
            float ov = s_bv[tid + s]; int oi = s_bi[tid + s];
            if (ov > s_bv[tid] || (ov == s_bv[tid] && oi < s_bi[tid])) {
                s_bv[tid] = ov; s_bi[tid] = oi;
            }
        }
        __syncthreads();
    }
    if (tid == 0) {
        if (s_bi[0] == labels[q]) atomicAdd(&g_correct, 1);
        __threadfence();
        int done = atomicAdd(&g_done, 1);
        if (done == NQ - 1) {
            // last block: all g_correct updates are visible
            out[0] = (float)g_correct * (1.0f / (float)NQ);
            out[OUT_PTR_OFF] = (float)((qptr[0] + NQ) % KQ);
        }
    }
}

// ---------------- kernel 5: queue update copy (concurrent side stream) -------
__global__ void __launch_bounds__(256)
copy_kernel(const float* __restrict__ feats, const int* __restrict__ labels,
            const float* __restrict__ qf, const int* __restrict__ ql,
            const int* __restrict__ qptr, float* __restrict__ out) {
    const int ptr = qptr[0];
    size_t i4 = (size_t)blockIdx.x * 256 + threadIdx.x;
    if (i4 < (size_t)(NF / 4)) {
        int r = (int)(i4 >> 6);
        int rel = r - ptr; if (rel < 0) rel += KQ;
        float4 v = (rel < NQ) ? ((const float4*)feats)[(size_t)rel * 64 + (i4 & 63)]
                              : ((const float4*)qf)[i4];
        float* o = out + OUT_FEAT_OFF + i4 * 4;
        o[0] = v.x; o[1] = v.y; o[2] = v.z; o[3] = v.w;
    } else if (i4 < (size_t)(NF / 4 + NL / 4)) {
        int j4 = (int)(i4 - NF / 4);
        int4 lv = ((const int4*)ql)[j4];
        int base = j4 * 4;
        float* o = out + OUT_LAB_OFF + base;
        #pragma unroll
        for (int k = 0; k < 4; k++) {
            int i = base + k;
            int rel = i - ptr; if (rel < 0) rel += KQ;
            int lab = (rel < NQ) ? labels[rel] : ((const int*)&lv)[k];
            o[k] = (float)lab;
        }
    }
}

// ---------------- launch ----------------
extern "C" void kernel_launch(void* const* d_in, const int* in_sizes, int n_in,
                              void* d_out, int out_size) {
    const float* feats  = (const float*)d_in[0];
    const int*   labels = (const int*)d_in[1];
    const float* qf     = (const float*)d_in[2];
    const int*   ql     = (const int*)d_in[3];
    const int*   qptr   = (const int*)d_in[4];
    float* out = (float*)d_out;

    cudaFuncSetAttribute(gemm_tc_kernel, cudaFuncAttributeMaxDynamicSharedMemorySize, GEMM_SMEM);
    cudaFuncSetAttribute(topk_kernel, cudaFuncAttributeMaxDynamicSharedMemorySize, TOPK_SMEM);

    // lazy one-time side-stream setup (host objects only; no device memory)
    static cudaStream_t s2 = nullptr;
    static cudaEvent_t evF = nullptr, evJ = nullptr;
    static bool tried = false;
    if (!tried) {
        tried = true;
        if (cudaStreamCreateWithFlags(&s2, cudaStreamNonBlocking) != cudaSuccess) s2 = nullptr;
        if (s2) {
            if (cudaEventCreateWithFlags(&evF, cudaEventDisableTiming) != cudaSuccess ||
                cudaEventCreateWithFlags(&evJ, cudaEventDisableTiming) != cudaSuccess) {
                s2 = nullptr;
            }
        }
    }

    int total4 = NF / 4 + NL / 4;
    int copy_blocks = (total4 + 255) / 256;

    if (s2) {
        // fork: copy depends only on inputs -> run concurrently with the pipeline
        cudaEventRecord(evF, 0);
        cudaStreamWaitEvent(s2, evF, 0);
        copy_kernel<<<copy_blocks, 256, 0, s2>>>(feats, labels, qf, ql, qptr, out);
        cudaEventRecord(evJ, s2);
    }

    convert_kernel<<<(BGROUPS + AGROUPS + 255) / 256, 256>>>(feats, qf);
    gemm_tc_kernel<<<dim3(NQ / TM, KQ / TN), 256, GEMM_SMEM>>>();
    rescue_kernel<<<NQ * RESCUE_SPLIT, 256>>>(feats, qf);

    if (s2) cudaStreamWaitEvent(0, evJ, 0);    // join copy before the final kernel
    topk_kernel<<<NQ, 256, TOPK_SMEM>>>(ql, labels, feats, qf, qptr, out);

    if (!s2) copy_kernel<<<copy_blocks, 256>>>(feats, labels, qf, ql, qptr, out);
    (void)in_sizes; (void)n_in; (void)out_size;
}